// round 1
// baseline (speedup 1.0000x reference)
#include <cuda_runtime.h>

// Problem constants (fixed shapes from reference setup_inputs)
#define BB 64
#define CC 256
#define TT 2048
#define N_PER_CH (BB * TT)          // 131072 samples per channel
#define CT (CC * TT)                // 524288
#define CT4 (CT / 4)                // 131072 float4 per [C,T] plane
#define TOTAL4 (BB * CT / 4)        // 8388608 float4 total
#define EPS 1e-4f

// Device scratch (allocation-free rule: __device__ globals)
__device__ float g_sum[CC];
__device__ float g_sumsq[CC];
__device__ float g_A[CT];           // [C, T] layout: scale  = rs[c]*gamma[t,c]
__device__ float g_Boff[CT];        // [C, T] layout: offset = beta[t,c] - mean[c]*scale

// ---------------------------------------------------------------------------
// Kernel 0: zero the accumulators (graph replays need deterministic state)
// ---------------------------------------------------------------------------
__global__ void zero_kernel() {
    int i = threadIdx.x;
    if (i < CC) {
        g_sum[i] = 0.0f;
        g_sumsq[i] = 0.0f;
    }
}

// ---------------------------------------------------------------------------
// Kernel 1: per-channel sum / sumsq. One block per (b,c) row of 2048 floats.
// 256 threads x 2 float4 each = 512 float4 = 2048 floats.
// ---------------------------------------------------------------------------
__global__ __launch_bounds__(256) void reduce_kernel(const float4* __restrict__ x) {
    const int row = blockIdx.x;            // row = b*CC + c
    const int c = row & (CC - 1);
    const float4* p = x + (size_t)row * (TT / 4);

    float s = 0.0f, sq = 0.0f;
#pragma unroll
    for (int k = 0; k < 2; k++) {
        float4 v = __ldcs(&p[threadIdx.x + k * 256]);   // streaming: don't pollute L2
        s  += (v.x + v.y) + (v.z + v.w);
        sq += (v.x * v.x + v.y * v.y) + (v.z * v.z + v.w * v.w);
    }

    // warp reduce
#pragma unroll
    for (int off = 16; off > 0; off >>= 1) {
        s  += __shfl_down_sync(0xFFFFFFFFu, s,  off);
        sq += __shfl_down_sync(0xFFFFFFFFu, sq, off);
    }

    __shared__ float ws[8], wq[8];
    const int warp = threadIdx.x >> 5;
    const int lane = threadIdx.x & 31;
    if (lane == 0) { ws[warp] = s; wq[warp] = sq; }
    __syncthreads();

    if (warp == 0) {
        s  = (lane < 8) ? ws[lane] : 0.0f;
        sq = (lane < 8) ? wq[lane] : 0.0f;
#pragma unroll
        for (int off = 4; off > 0; off >>= 1) {
            s  += __shfl_down_sync(0xFFFFFFFFu, s,  off);
            sq += __shfl_down_sync(0xFFFFFFFFu, sq, off);
        }
        if (lane == 0) {
            atomicAdd(&g_sum[c],   s);
            atomicAdd(&g_sumsq[c], sq);
        }
    }
}

// ---------------------------------------------------------------------------
// Kernel 2: build fused affine A/B in [C, T] layout (transpose gamma/beta
// from [T, C] via 32x32 shared tile).
//   A[c][t] = rs[c] * gamma[t][c]
//   B[c][t] = beta[t][c] - mean[c] * A[c][t]
// Grid: (CC/32, TT/32), block (32, 8).
// ---------------------------------------------------------------------------
__global__ __launch_bounds__(256) void prep_kernel(const float* __restrict__ gamma,
                                                   const float* __restrict__ beta) {
    __shared__ float sg[32][33];
    __shared__ float sb[32][33];

    const int cBase = blockIdx.x * 32;
    const int tBase = blockIdx.y * 32;

    // load: rows = t, cols = c (coalesced over c)
#pragma unroll
    for (int r = 0; r < 4; r++) {
        const int tl = threadIdx.y + r * 8;
        const int t = tBase + tl;
        const int c = cBase + threadIdx.x;
        sg[tl][threadIdx.x] = gamma[t * CC + c];
        sb[tl][threadIdx.x] = beta[t * CC + c];
    }
    __syncthreads();

    // write: rows = c, cols = t (coalesced over t)
#pragma unroll
    for (int r = 0; r < 4; r++) {
        const int cl = threadIdx.y + r * 8;
        const int c = cBase + cl;
        const int t = tBase + threadIdx.x;

        const float inv_n = 1.0f / (float)N_PER_CH;
        const float mean = g_sum[c] * inv_n;
        const float var = fmaxf(g_sumsq[c] * inv_n - mean * mean, 0.0f);
        const float rs = rsqrtf(var + EPS);

        const float gv = sg[threadIdx.x][cl];
        const float bv = sb[threadIdx.x][cl];
        const float a = gv * rs;
        g_A[c * TT + t] = a;
        g_Boff[c * TT + t] = bv - mean * a;
    }
}

// ---------------------------------------------------------------------------
// Kernel 3: elementwise out[i] = x[i] * A[j] + B[j], j = i mod (C*T).
// float4 vectorized; x/out streaming so A/B (4 MiB) stay L2-resident
// across the B=64 reuse.
// ---------------------------------------------------------------------------
__global__ __launch_bounds__(256) void norm_kernel(const float4* __restrict__ x,
                                                   float4* __restrict__ out) {
    const unsigned i = blockIdx.x * 256u + threadIdx.x;   // < TOTAL4 = 2^23
    const unsigned j = i & (CT4 - 1u);

    const float4* __restrict__ A4 = (const float4*)g_A;
    const float4* __restrict__ B4 = (const float4*)g_Boff;

    float4 v = __ldcs(&x[i]);
    float4 a = __ldg(&A4[j]);
    float4 b = __ldg(&B4[j]);

    float4 o;
    o.x = fmaf(v.x, a.x, b.x);
    o.y = fmaf(v.y, a.y, b.y);
    o.z = fmaf(v.z, a.z, b.z);
    o.w = fmaf(v.w, a.w, b.w);
    __stcs(&out[i], o);
}

// ---------------------------------------------------------------------------
extern "C" void kernel_launch(void* const* d_in, const int* in_sizes, int n_in,
                              void* d_out, int out_size) {
    const float* x = (const float*)d_in[0];
    const float* gamma = (const float*)d_in[1];
    const float* beta = (const float*)d_in[2];
    float* out = (float*)d_out;

    zero_kernel<<<1, 256>>>();
    reduce_kernel<<<BB * CC, 256>>>((const float4*)x);
    {
        dim3 grid(CC / 32, TT / 32);
        dim3 block(32, 8);
        prep_kernel<<<grid, block>>>(gamma, beta);
    }
    norm_kernel<<<TOTAL4 / 256, 256>>>((const float4*)x, (float4*)out);
}